// round 1
// baseline (speedup 1.0000x reference)
#include <cuda_runtime.h>
#include <math.h>

#define BATCH 64
#define H 64
#define W 96
#define HW (H * W)
#define UV 81
#define NCH 16

// ln(49), ln(81)
#define INV_LN49 0.25694882f   // 1/3.8918203
#define INV_LN81 0.22756237f   // 1/4.3944492

__global__ __launch_bounds__(256) void segnet_flowreg_warp_kernel(
    const float* __restrict__ cost,
    const float* __restrict__ feat,
    float* __restrict__ out)
{
    int idx = blockIdx.x * blockDim.x + threadIdx.x;   // b*HW + h*W + w
    if (idx >= BATCH * HW) return;
    int b  = idx / HW;
    int hw = idx - b * HW;
    int h  = hw / W;
    int w  = hw - h * W;

    // ---- load 81 cost values (coalesced per (u,v) slice), track argmax ----
    const float* cp = cost + (size_t)b * UV * HW + hw;
    float c[UV];
    float m = -INFINITY;
    int   am = 0;
#pragma unroll
    for (int i = 0; i < UV; i++) {
        float v = __ldg(cp + (size_t)i * HW);
        c[i] = v;
        if (v > m) { m = v; am = i; }   // strict > keeps first occurrence (jnp.argmax)
    }
    int u0 = am / 9;
    int v0 = am - u0 * 9;

    // ---- single exp pass: global + truncated-window sums.
    //      window max == global max (argmax is inside its own window). ----
    float Sg = 0.f, Sg1 = 0.f;          // global softmax: sum e, sum e*d
    float Sw = 0.f, Sw1 = 0.f;          // window sums
    float Sx = 0.f, Sy = 0.f;           // window moments
#pragma unroll
    for (int i = 0; i < UV; i++) {
        const int u = i / 9;
        const int v = i - u * 9;
        float d = c[i] - m;
        float e = __expf(d);
        Sg  += e;
        Sg1 += e * d;
        bool inw = (u - u0 <= 3) && (u0 - u <= 3) && (v - v0 <= 3) && (v0 - v <= 3);
        if (inw) {
            Sw  += e;
            Sw1 += e * d;
            Sx  += e * (float)(u - 4);
            Sy  += e * (float)(v - 4);
        }
    }
    float invSw = 1.0f / Sw;
    float fx = Sx * invSw;                               // flow[:,0] = E[u-4]
    float fy = Sy * invSw;                               // flow[:,1] = E[v-4]
    float lent = (logf(Sw) - Sw1 * invSw) * INV_LN49;    // local entropy
    float gent = (logf(Sg) - Sg1 / Sg)    * INV_LN81;    // global entropy

    // ---- write flow + ent ----
    float* flow_o = out;
    float* ent_o  = out + (size_t)BATCH * 2 * HW;
    float* warp_o = out + (size_t)BATCH * 4 * HW;
    flow_o[((size_t)b * 2 + 0) * HW + hw] = fx;
    flow_o[((size_t)b * 2 + 1) * HW + hw] = fy;
    ent_o [((size_t)b * 2 + 0) * HW + hw] = lent;
    ent_o [((size_t)b * 2 + 1) * HW + hw] = gent;

    // ---- bilinear backward warp of feat (align_corners=True, zero pad) ----
    float px = (float)w + fx;
    float py = (float)h + fy;
    float x0f = floorf(px), y0f = floorf(py);
    float wx = px - x0f,   wy = py - y0f;
    int x0 = (int)x0f, y0 = (int)y0f;
    int x1 = x0 + 1,   y1 = y0 + 1;
    bool vx0 = (x0 >= 0) & (x0 < W);
    bool vx1 = (x1 >= 0) & (x1 < W);
    bool vy0 = (y0 >= 0) & (y0 < H);
    bool vy1 = (y1 >= 0) & (y1 < H);

    float w00 = (1.f - wx) * (1.f - wy) * ((vx0 & vy0) ? 1.f : 0.f);
    float w01 = wx         * (1.f - wy) * ((vx1 & vy0) ? 1.f : 0.f);
    float w10 = (1.f - wx) * wy         * ((vx0 & vy1) ? 1.f : 0.f);
    float w11 = wx         * wy         * ((vx1 & vy1) ? 1.f : 0.f);

    // in-bounds mask: |2*px/(W-1)-1| < 1  <=>  0 < px < W-1 (strict)
    float nx = 2.f * px / (float)(W - 1) - 1.f;
    float ny = 2.f * py / (float)(H - 1) - 1.f;
    float msk = (fabsf(nx) < 1.f && fabsf(ny) < 1.f) ? 1.f : 0.f;
    w00 *= msk; w01 *= msk; w10 *= msk; w11 *= msk;

    int x0c = min(max(x0, 0), W - 1), x1c = min(max(x1, 0), W - 1);
    int y0c = min(max(y0, 0), H - 1), y1c = min(max(y1, 0), H - 1);
    int o00 = y0c * W + x0c, o01 = y0c * W + x1c;
    int o10 = y1c * W + x0c, o11 = y1c * W + x1c;

    const float* fb = feat + (size_t)b * NCH * HW;
#pragma unroll
    for (int ch = 0; ch < NCH; ch++) {
        const float* f = fb + ch * HW;
        float val = w00 * __ldg(f + o00) + w01 * __ldg(f + o01)
                  + w10 * __ldg(f + o10) + w11 * __ldg(f + o11);
        warp_o[((size_t)b * NCH + ch) * HW + hw] = val;
    }
}

extern "C" void kernel_launch(void* const* d_in, const int* in_sizes, int n_in,
                              void* d_out, int out_size) {
    const float* cost = (const float*)d_in[0];
    const float* feat = (const float*)d_in[1];
    // d_in[2] is maxdisp (int scalar) — fixed at 4, shapes hardcoded.
    float* out = (float*)d_out;

    int total = BATCH * HW;                 // 393216 threads, 1 per pixel
    int threads = 256;
    int blocks = (total + threads - 1) / threads;
    segnet_flowreg_warp_kernel<<<blocks, threads>>>(cost, feat, out);
}